// round 16
// baseline (speedup 1.0000x reference)
#include <cuda_runtime.h>

#define C     10
#define C2    20
#define HW    128
#define TW    32
#define TH    16
#define PITCH 36            // EVEN pitch -> 8B-aligned rows for LDS.64 (conflict-free per phase)
#define HALOH 18
#define HS    (PITCH*HALOH) // 648
#define NTHR  256

typedef unsigned long long ull;

// shared layout (floats)
#define OFF_F     0
#define OFF_H0    (C*HS)                    // 6480
#define OFF_H1    (2*C*HS)                  // 12960
#define OFF_WREL  (3*C*HS)                  // 19440 (x4B, 16B aligned)
#define OFF_WG2   (OFF_WREL + 450*4)        // 21240
#define OFF_WC2   (OFF_WG2 + 200*4)         // 22040
#define OFF_GB    (OFF_WC2 + 100*4)         // 22440
#define OFF_CB    (OFF_GB + C2)             // 22460
#define OFF_B2    (OFF_CB + C)              // 22470
#define SMEM_FLOATS (OFF_B2 + C)            // 22480
#define SMEM_BYTES (SMEM_FLOATS*4)          // ~89.9 KB

// HW tanh (MUFU.TANH; abs err ~5e-4 << 1e-3 threshold)
__device__ __forceinline__ float htanh(float x) {
    float r; asm("tanh.approx.f32 %0, %1;" : "=f"(r) : "f"(x)); return r;
}
__device__ __forceinline__ float fsigmoid(float x) {
    return fmaf(0.5f, htanh(0.5f * x), 0.5f);
}

__device__ __forceinline__ ull pack2(float lo, float hi) {
    ull r; asm("mov.b64 %0, {%1,%2};" : "=l"(r) : "f"(lo), "f"(hi)); return r;
}
__device__ __forceinline__ void unpack2(ull v, float& lo, float& hi) {
    asm("mov.b64 {%0,%1}, %2;" : "=f"(lo), "=f"(hi) : "l"(v));
}
__device__ __forceinline__ void fma2(ull& acc, ull a, ull b) {
    asm("fma.rn.f32x2 %0, %1, %2, %0;" : "+l"(acc) : "l"(a), "l"(b));
}
__device__ __forceinline__ ull mul2(ull a, ull b) {
    ull r; asm("mul.rn.f32x2 %0, %1, %2;" : "=l"(r) : "l"(a), "l"(b)); return r;
}

__global__ void __launch_bounds__(NTHR, 1)   // <- 255-reg budget; let ptxas pipeline deeply
fused_tree_gru(const float* __restrict__ f_node,
               const float* __restrict__ h0g,
               const float* __restrict__ h1g,
               const float* __restrict__ att_w,
               const float* __restrict__ att_b,
               const float* __restrict__ rel_w,
               const float* __restrict__ bn_gamma,
               const float* __restrict__ bn_beta,
               const float* __restrict__ bn_mean,
               const float* __restrict__ bn_var,
               const float* __restrict__ gates_w,
               const float* __restrict__ gates_b,
               const float* __restrict__ can_w,
               const float* __restrict__ can_b,
               float* __restrict__ out_f,
               float* __restrict__ out_att)
{
    extern __shared__ float sm[];
    float* f_s   = sm + OFF_F;
    float* h0_s  = sm + OFF_H0;
    float* h1_s  = sm + OFF_H1;
    float* wrel  = sm + OFF_WREL;
    float* wg2   = sm + OFF_WG2;
    float* wc2   = sm + OFF_WC2;
    float* gb_s  = sm + OFF_GB;
    float* cb_s  = sm + OFF_CB;
    float* b2_s  = sm + OFF_B2;

    const int tid = threadIdx.x;
    const int b   = blockIdx.z;
    const int tx0 = blockIdx.x * TW;
    const int ty0 = blockIdx.y * TH;

    // ---- stage weights (folded, co-pair packed) ----
    for (int e = tid; e < C*9*5; e += NTHR) {
        int cp = e % 5;
        int k  = (e / 5) % 9;
        int ci = e / 45;
        int coA = 2*cp, coB = 2*cp + 1;
        float invA = bn_gamma[coA] * rsqrtf(bn_var[coA] + 1e-5f);
        float invB = bn_gamma[coB] * rsqrtf(bn_var[coB] + 1e-5f);
        float* d = wrel + e*4;
        d[0] = rel_w[(coA*C2 + ci)*9 + k] * invA;
        d[1] = rel_w[(coB*C2 + ci)*9 + k] * invB;
        d[2] = rel_w[(coA*C2 + C + ci)*9 + k] * invA;
        d[3] = rel_w[(coB*C2 + C + ci)*9 + k] * invB;
    }
    for (int e = tid; e < C2*C; e += NTHR) {
        int co = e / C, ci = e % C;
        float w1 = gates_w[co*C2 + ci];
        float w2 = gates_w[co*C2 + C + ci];
        float* d = wg2 + e*4;
        d[0] = w1; d[1] = w1; d[2] = w2; d[3] = w2;
    }
    if (tid < C*C) {
        int co = tid / C, ci = tid % C;
        float w1 = can_w[co*C2 + ci];
        float w2 = can_w[co*C2 + C + ci];
        float* d = wc2 + tid*4;
        d[0] = w1; d[1] = w1; d[2] = w2; d[3] = w2;
    }
    if (tid < C2) gb_s[tid] = gates_b[tid];
    if (tid < C) {
        cb_s[tid] = can_b[tid];
        float inv = bn_gamma[tid] * rsqrtf(bn_var[tid] + 1e-5f);
        b2_s[tid] = bn_beta[tid] - bn_mean[tid] * inv;
    }

    // ---- fused prologue: load halo tiles + inline attention scaling ----
    {
        const float ab = __ldg(att_b);
        for (int i = tid; i < 18*18; i += NTHR) {
            int ly = i / 18, slot = i - ly*18;
            int gy = ty0 - 1 + ly;
            bool okr = (gy >= 0) & (gy < HW);
            if (slot == 0 || slot == 17) {
                int lx = (slot == 0) ? 0 : 33;
                int gx = tx0 - 1 + lx;
                bool ok = okr & (gx >= 0) & (gx < HW);
                long gbase = ((long)(b*C)*HW + gy)*HW + gx;
                int  sbase = ly*PITCH + lx;
                float v0[C], v1[C];
                float s = ab;
                #pragma unroll
                for (int ci = 0; ci < C; ++ci) {
                    long gi = gbase + (long)ci*HW*HW;
                    f_s[ci*HS + sbase] = ok ? f_node[gi] : 0.f;
                    v0[ci] = ok ? h0g[gi] : 0.f;
                    v1[ci] = ok ? h1g[gi] : 0.f;
                    s += __ldg(att_w + ci)*v0[ci] + __ldg(att_w + C + ci)*v1[ci];
                }
                float a = fsigmoid(s);
                #pragma unroll
                for (int ci = 0; ci < C; ++ci) {
                    h0_s[ci*HS + sbase] = v0[ci]*a;
                    h1_s[ci*HS + sbase] = v1[ci]*a;
                }
            } else {
                int lx = 2*slot - 1;             // 1,3,...,31
                int gx = tx0 - 1 + lx;           // even, in [0,126]
                long gbase = ((long)(b*C)*HW + gy)*HW + gx;
                int  sbase = ly*PITCH + lx;
                float2 v0[C], v1[C];
                float s0 = ab, s1 = ab;
                #pragma unroll
                for (int ci = 0; ci < C; ++ci) {
                    long gi = gbase + (long)ci*HW*HW;
                    float2 vf = okr ? *reinterpret_cast<const float2*>(f_node + gi) : make_float2(0.f,0.f);
                    v0[ci]    = okr ? *reinterpret_cast<const float2*>(h0g + gi)    : make_float2(0.f,0.f);
                    v1[ci]    = okr ? *reinterpret_cast<const float2*>(h1g + gi)    : make_float2(0.f,0.f);
                    int si = ci*HS + sbase;
                    f_s[si] = vf.x; f_s[si+1] = vf.y;
                    float aw0 = __ldg(att_w + ci), aw1 = __ldg(att_w + C + ci);
                    s0 += aw0*v0[ci].x + aw1*v1[ci].x;
                    s1 += aw0*v0[ci].y + aw1*v1[ci].y;
                }
                float a0 = fsigmoid(s0), a1 = fsigmoid(s1);
                #pragma unroll
                for (int ci = 0; ci < C; ++ci) {
                    int si = ci*HS + sbase;
                    h0_s[si] = v0[ci].x*a0; h0_s[si+1] = v0[ci].y*a1;
                    h1_s[si] = v1[ci].x*a0; h1_s[si+1] = v1[ci].y*a1;
                }
                if (ly >= 1 && ly <= TH) {
                    long ao = ((long)b*HW + gy)*HW + gx;
                    *reinterpret_cast<float2*>(out_att + ao) = make_float2(a0, a1);
                }
            }
        }
    }
    __syncthreads();

    // ---- 3x3 conv: LDS.64 data loads (even pitch -> aligned), fc harvest ----
    const int txp  = (tid & 15) * 2;   // even
    const int ty   = tid >> 4;
    const int base = ty*PITCH + txp;   // even: PITCH even, txp even

    ull accf[5][2], acc0[5][2], acc1[5][2];
    #pragma unroll
    for (int cp = 0; cp < 5; ++cp) {
        ull bz = pack2(b2_s[2*cp], b2_s[2*cp+1]);
        accf[cp][0] = bz; accf[cp][1] = bz;
        acc0[cp][0] = acc0[cp][1] = 0ull;
        acc1[cp][0] = acc1[cp][1] = 0ull;
    }

    ull fc01[C];
    for (int ci = 0; ci < C; ++ci) {
        const float* fb  = f_s  + ci*HS + base;
        const float* h0b = h0_s + ci*HS + base;
        const float* h1b = h1_s + ci*HS + base;
        const ulonglong2* wci = reinterpret_cast<const ulonglong2*>(wrel) + ci*45;
        #pragma unroll
        for (int r = 0; r < 3; ++r) {
            const int ro = r*PITCH;
            ull fpA = *reinterpret_cast<const ull*>(fb + ro);
            ull fpB = *reinterpret_cast<const ull*>(fb + ro + 2);
            ull gpA = *reinterpret_cast<const ull*>(h0b + ro);
            ull gpB = *reinterpret_cast<const ull*>(h0b + ro + 2);
            ull epA = *reinterpret_cast<const ull*>(h1b + ro);
            ull epB = *reinterpret_cast<const ull*>(h1b + ro + 2);
            float f0,f1,f2,f3, g0,g1,g2,g3, e0,e1,e2,e3;
            unpack2(fpA, f0, f1); unpack2(fpB, f2, f3);
            unpack2(gpA, g0, g1); unpack2(gpB, g2, g3);
            unpack2(epA, e0, e1); unpack2(epB, e2, e3);
            if (r == 1) fc01[ci] = pack2(f1, f2);   // center f pair, free harvest
            ull fd[4] = { pack2(f0,f0), pack2(f1,f1), pack2(f2,f2), pack2(f3,f3) };
            ull gd[4] = { pack2(g0,g0), pack2(g1,g1), pack2(g2,g2), pack2(g3,g3) };
            ull ed[4] = { pack2(e0,e0), pack2(e1,e1), pack2(e2,e2), pack2(e3,e3) };
            #pragma unroll
            for (int kx = 0; kx < 3; ++kx) {
                const ulonglong2* wk = wci + (r*3 + kx)*5;
                #pragma unroll
                for (int cp = 0; cp < 5; ++cp) {
                    ulonglong2 w = wk[cp];   // .x={wfA,wfB} .y={whA,whB}
                    fma2(accf[cp][0], w.x, fd[kx]);
                    fma2(accf[cp][1], w.x, fd[kx+1]);
                    fma2(acc0[cp][0], w.y, gd[kx]);
                    fma2(acc0[cp][1], w.y, gd[kx+1]);
                    fma2(acc1[cp][0], w.y, ed[kx]);
                    fma2(acc1[cp][1], w.y, ed[kx+1]);
                }
            }
        }
    }

    // ---- epilogue: ReLU + sum -> packed comp_h ----
    ull ch01[C];
    #pragma unroll
    for (int cp = 0; cp < 5; ++cp) {
        float chv[2][2];
        #pragma unroll
        for (int px = 0; px < 2; ++px) {
            float afA, afB, x0A, x0B, x1A, x1B;
            unpack2(accf[cp][px], afA, afB);
            unpack2(acc0[cp][px], x0A, x0B);
            unpack2(acc1[cp][px], x1A, x1B);
            chv[px][0] = fmaxf(afA + x0A, 0.f) + fmaxf(afA + x1A, 0.f);
            chv[px][1] = fmaxf(afB + x0B, 0.f) + fmaxf(afB + x1B, 0.f);
        }
        ch01[2*cp]   = pack2(chv[0][0], chv[1][0]);
        ch01[2*cp+1] = pack2(chv[0][1], chv[1][1]);
    }

    // ---- ConvGRU gates (1x1), packed f32x2, HW tanh sigmoids ----
    ull r01[C], u01[C];
    #pragma unroll
    for (int co = 0; co < C2; ++co) {
        float gb = gb_s[co];
        ull g = pack2(gb, gb);
        const ulonglong2* w = reinterpret_cast<const ulonglong2*>(wg2) + co*C;
        #pragma unroll
        for (int ci = 0; ci < C; ++ci) {
            ulonglong2 ww = w[ci];
            fma2(g, ww.x, ch01[ci]);
            fma2(g, ww.y, fc01[ci]);
        }
        float gg0, gg1; unpack2(g, gg0, gg1);
        ull s = pack2(fsigmoid(gg0), fsigmoid(gg1));
        if (co < C) r01[co] = s; else u01[co - C] = s;
    }
    ull rf01[C];
    #pragma unroll
    for (int ci = 0; ci < C; ++ci) rf01[ci] = mul2(r01[ci], fc01[ci]);

    // ---- candidate + update, write output ----
    const int gy = ty0 + ty, gx = tx0 + txp;
    #pragma unroll
    for (int co = 0; co < C; ++co) {
        float cb = cb_s[co];
        ull g = pack2(cb, cb);
        const ulonglong2* w = reinterpret_cast<const ulonglong2*>(wc2) + co*C;
        #pragma unroll
        for (int ci = 0; ci < C; ++ci) {
            ulonglong2 ww = w[ci];
            fma2(g, ww.x, ch01[ci]);
            fma2(g, ww.y, rf01[ci]);
        }
        float gg0, gg1; unpack2(g, gg0, gg1);
        float t0 = htanh(gg0), t1 = htanh(gg1);
        float fc0, fc1; unpack2(fc01[co], fc0, fc1);
        float u0, u1;  unpack2(u01[co], u0, u1);
        float r0 = fc0 + u0*(t0 - fc0);
        float r1 = fc1 + u1*(t1 - fc1);
        long o = ((long)(b*C + co)*HW + gy)*HW + gx;
        *reinterpret_cast<float2*>(out_f + o) = make_float2(r0, r1);
    }
}

extern "C" void kernel_launch(void* const* d_in, const int* in_sizes, int n_in,
                              void* d_out, int out_size) {
    (void)n_in; (void)out_size;
    const float* f_node   = (const float*)d_in[0];
    const float* h0       = (const float*)d_in[1];
    const float* h1       = (const float*)d_in[2];
    // d_in[3] = p_nodes (unused), d_in[4] = xf (unused)
    const float* att_w    = (const float*)d_in[5];
    const float* att_b    = (const float*)d_in[6];
    const float* rel_w    = (const float*)d_in[7];
    const float* bn_gamma = (const float*)d_in[8];
    const float* bn_beta  = (const float*)d_in[9];
    const float* bn_mean  = (const float*)d_in[10];
    const float* bn_var   = (const float*)d_in[11];
    const float* gates_w  = (const float*)d_in[12];
    const float* gates_b  = (const float*)d_in[13];
    const float* can_w    = (const float*)d_in[14];
    const float* can_b    = (const float*)d_in[15];

    int B = in_sizes[0] / (C * HW * HW);
    float* out_f   = (float*)d_out;
    float* out_att = out_f + (long)B * C * HW * HW;

    static bool attr_set = false;
    if (!attr_set) {
        cudaFuncSetAttribute(fused_tree_gru,
                             cudaFuncAttributeMaxDynamicSharedMemorySize, SMEM_BYTES);
        attr_set = true;
    }

    dim3 grid(HW / TW, HW / TH, B);
    fused_tree_gru<<<grid, NTHR, SMEM_BYTES>>>(f_node, h0, h1, att_w, att_b, rel_w,
                                               bn_gamma, bn_beta, bn_mean, bn_var,
                                               gates_w, gates_b, can_w, can_b,
                                               out_f, out_att);
}

// round 17
// speedup vs baseline: 1.0703x; 1.0703x over previous
#include <cuda_runtime.h>

#define C     10
#define C2    20
#define HW    128
#define TW    32
#define TH    16
#define PITCH 36            // EVEN pitch -> 8B-aligned rows for LDS.64
#define HALOH 18
#define HS    (PITCH*HALOH) // 648
#define NTHR  256

typedef unsigned long long ull;

// shared layout (floats)
#define OFF_F     0
#define OFF_H0    (C*HS)                    // 6480
#define OFF_H1    (2*C*HS)                  // 12960
#define OFF_WREL  (3*C*HS)                  // 19440 (x4B, 16B aligned)
#define OFF_WG2   (OFF_WREL + 450*4)        // 21240
#define OFF_WC2   (OFF_WG2 + 200*4)         // 22040
#define OFF_GB    (OFF_WC2 + 100*4)         // 22440
#define OFF_CB    (OFF_GB + C2)             // 22460
#define OFF_B2    (OFF_CB + C)              // 22470
#define SMEM_FLOATS (OFF_B2 + C)            // 22480
#define SMEM_BYTES (SMEM_FLOATS*4)          // ~89.9 KB

// HW tanh (MUFU.TANH; abs err ~5e-4 << 1e-3 threshold)
__device__ __forceinline__ float htanh(float x) {
    float r; asm("tanh.approx.f32 %0, %1;" : "=f"(r) : "f"(x)); return r;
}
__device__ __forceinline__ float fsigmoid(float x) {
    return fmaf(0.5f, htanh(0.5f * x), 0.5f);
}

__device__ __forceinline__ ull pack2(float lo, float hi) {
    ull r; asm("mov.b64 %0, {%1,%2};" : "=l"(r) : "f"(lo), "f"(hi)); return r;
}
__device__ __forceinline__ void unpack2(ull v, float& lo, float& hi) {
    asm("mov.b64 {%0,%1}, %2;" : "=f"(lo), "=f"(hi) : "l"(v));
}
__device__ __forceinline__ void fma2(ull& acc, ull a, ull b) {
    asm("fma.rn.f32x2 %0, %1, %2, %0;" : "+l"(acc) : "l"(a), "l"(b));
}
__device__ __forceinline__ ull mul2(ull a, ull b) {
    ull r; asm("mul.rn.f32x2 %0, %1, %2;" : "=l"(r) : "l"(a), "l"(b)); return r;
}

__global__ void __launch_bounds__(NTHR, 2)
fused_tree_gru(const float* __restrict__ f_node,
               const float* __restrict__ h0g,
               const float* __restrict__ h1g,
               const float* __restrict__ att_w,
               const float* __restrict__ att_b,
               const float* __restrict__ rel_w,
               const float* __restrict__ bn_gamma,
               const float* __restrict__ bn_beta,
               const float* __restrict__ bn_mean,
               const float* __restrict__ bn_var,
               const float* __restrict__ gates_w,
               const float* __restrict__ gates_b,
               const float* __restrict__ can_w,
               const float* __restrict__ can_b,
               float* __restrict__ out_f,
               float* __restrict__ out_att)
{
    extern __shared__ float sm[];
    float* f_s   = sm + OFF_F;
    float* h0_s  = sm + OFF_H0;
    float* h1_s  = sm + OFF_H1;
    float* wrel  = sm + OFF_WREL;
    float* wg2   = sm + OFF_WG2;
    float* wc2   = sm + OFF_WC2;
    float* gb_s  = sm + OFF_GB;
    float* cb_s  = sm + OFF_CB;
    float* b2_s  = sm + OFF_B2;

    const int tid = threadIdx.x;
    const int b   = blockIdx.z;
    const int tx0 = blockIdx.x * TW;
    const int ty0 = blockIdx.y * TH;

    // ---- stage weights (folded, co-pair packed) ----
    for (int e = tid; e < C*9*5; e += NTHR) {
        int cp = e % 5;
        int k  = (e / 5) % 9;
        int ci = e / 45;
        int coA = 2*cp, coB = 2*cp + 1;
        float invA = bn_gamma[coA] * rsqrtf(bn_var[coA] + 1e-5f);
        float invB = bn_gamma[coB] * rsqrtf(bn_var[coB] + 1e-5f);
        float* d = wrel + e*4;
        d[0] = rel_w[(coA*C2 + ci)*9 + k] * invA;
        d[1] = rel_w[(coB*C2 + ci)*9 + k] * invB;
        d[2] = rel_w[(coA*C2 + C + ci)*9 + k] * invA;
        d[3] = rel_w[(coB*C2 + C + ci)*9 + k] * invB;
    }
    for (int e = tid; e < C2*C; e += NTHR) {
        int co = e / C, ci = e % C;
        float w1 = gates_w[co*C2 + ci];
        float w2 = gates_w[co*C2 + C + ci];
        float* d = wg2 + e*4;
        d[0] = w1; d[1] = w1; d[2] = w2; d[3] = w2;
    }
    if (tid < C*C) {
        int co = tid / C, ci = tid % C;
        float w1 = can_w[co*C2 + ci];
        float w2 = can_w[co*C2 + C + ci];
        float* d = wc2 + tid*4;
        d[0] = w1; d[1] = w1; d[2] = w2; d[3] = w2;
    }
    if (tid < C2) gb_s[tid] = gates_b[tid];
    if (tid < C) {
        cb_s[tid] = can_b[tid];
        float inv = bn_gamma[tid] * rsqrtf(bn_var[tid] + 1e-5f);
        b2_s[tid] = bn_beta[tid] - bn_mean[tid] * inv;
    }

    // ---- fused prologue: load halo tiles + inline attention scaling ----
    {
        const float ab = __ldg(att_b);
        for (int i = tid; i < 18*18; i += NTHR) {
            int ly = i / 18, slot = i - ly*18;
            int gy = ty0 - 1 + ly;
            bool okr = (gy >= 0) & (gy < HW);
            if (slot == 0 || slot == 17) {
                int lx = (slot == 0) ? 0 : 33;
                int gx = tx0 - 1 + lx;
                bool ok = okr & (gx >= 0) & (gx < HW);
                long gbase = ((long)(b*C)*HW + gy)*HW + gx;
                int  sbase = ly*PITCH + lx;
                float v0[C], v1[C];
                float s = ab;
                #pragma unroll
                for (int ci = 0; ci < C; ++ci) {
                    long gi = gbase + (long)ci*HW*HW;
                    f_s[ci*HS + sbase] = ok ? f_node[gi] : 0.f;
                    v0[ci] = ok ? h0g[gi] : 0.f;
                    v1[ci] = ok ? h1g[gi] : 0.f;
                    s += __ldg(att_w + ci)*v0[ci] + __ldg(att_w + C + ci)*v1[ci];
                }
                float a = fsigmoid(s);
                #pragma unroll
                for (int ci = 0; ci < C; ++ci) {
                    h0_s[ci*HS + sbase] = v0[ci]*a;
                    h1_s[ci*HS + sbase] = v1[ci]*a;
                }
            } else {
                int lx = 2*slot - 1;             // 1,3,...,31
                int gx = tx0 - 1 + lx;           // even, in [0,126]
                long gbase = ((long)(b*C)*HW + gy)*HW + gx;
                int  sbase = ly*PITCH + lx;
                float2 v0[C], v1[C];
                float s0 = ab, s1 = ab;
                #pragma unroll
                for (int ci = 0; ci < C; ++ci) {
                    long gi = gbase + (long)ci*HW*HW;
                    float2 vf = okr ? *reinterpret_cast<const float2*>(f_node + gi) : make_float2(0.f,0.f);
                    v0[ci]    = okr ? *reinterpret_cast<const float2*>(h0g + gi)    : make_float2(0.f,0.f);
                    v1[ci]    = okr ? *reinterpret_cast<const float2*>(h1g + gi)    : make_float2(0.f,0.f);
                    int si = ci*HS + sbase;
                    f_s[si] = vf.x; f_s[si+1] = vf.y;
                    float aw0 = __ldg(att_w + ci), aw1 = __ldg(att_w + C + ci);
                    s0 += aw0*v0[ci].x + aw1*v1[ci].x;
                    s1 += aw0*v0[ci].y + aw1*v1[ci].y;
                }
                float a0 = fsigmoid(s0), a1 = fsigmoid(s1);
                #pragma unroll
                for (int ci = 0; ci < C; ++ci) {
                    int si = ci*HS + sbase;
                    h0_s[si] = v0[ci].x*a0; h0_s[si+1] = v0[ci].y*a1;
                    h1_s[si] = v1[ci].x*a0; h1_s[si+1] = v1[ci].y*a1;
                }
                if (ly >= 1 && ly <= TH) {
                    long ao = ((long)b*HW + gy)*HW + gx;
                    *reinterpret_cast<float2*>(out_att + ao) = make_float2(a0, a1);
                }
            }
        }
    }
    __syncthreads();

    // ---- 3x3 conv: LDS.64 data loads; no fc harvest (regs freed for pipelining) ----
    const int txp  = (tid & 15) * 2;   // even
    const int ty   = tid >> 4;
    const int base = ty*PITCH + txp;   // even: PITCH even, txp even

    ull accf[5][2], acc0[5][2], acc1[5][2];
    #pragma unroll
    for (int cp = 0; cp < 5; ++cp) {
        ull bz = pack2(b2_s[2*cp], b2_s[2*cp+1]);
        accf[cp][0] = bz; accf[cp][1] = bz;
        acc0[cp][0] = acc0[cp][1] = 0ull;
        acc1[cp][0] = acc1[cp][1] = 0ull;
    }

    for (int ci = 0; ci < C; ++ci) {
        const float* fb  = f_s  + ci*HS + base;
        const float* h0b = h0_s + ci*HS + base;
        const float* h1b = h1_s + ci*HS + base;
        const ulonglong2* wci = reinterpret_cast<const ulonglong2*>(wrel) + ci*45;
        #pragma unroll
        for (int r = 0; r < 3; ++r) {
            const int ro = r*PITCH;
            ull fpA = *reinterpret_cast<const ull*>(fb + ro);
            ull fpB = *reinterpret_cast<const ull*>(fb + ro + 2);
            ull gpA = *reinterpret_cast<const ull*>(h0b + ro);
            ull gpB = *reinterpret_cast<const ull*>(h0b + ro + 2);
            ull epA = *reinterpret_cast<const ull*>(h1b + ro);
            ull epB = *reinterpret_cast<const ull*>(h1b + ro + 2);
            float f0,f1,f2,f3, g0,g1,g2,g3, e0,e1,e2,e3;
            unpack2(fpA, f0, f1); unpack2(fpB, f2, f3);
            unpack2(gpA, g0, g1); unpack2(gpB, g2, g3);
            unpack2(epA, e0, e1); unpack2(epB, e2, e3);
            ull fd[4] = { pack2(f0,f0), pack2(f1,f1), pack2(f2,f2), pack2(f3,f3) };
            ull gd[4] = { pack2(g0,g0), pack2(g1,g1), pack2(g2,g2), pack2(g3,g3) };
            ull ed[4] = { pack2(e0,e0), pack2(e1,e1), pack2(e2,e2), pack2(e3,e3) };
            #pragma unroll
            for (int kx = 0; kx < 3; ++kx) {
                const ulonglong2* wk = wci + (r*3 + kx)*5;
                #pragma unroll
                for (int cp = 0; cp < 5; ++cp) {
                    ulonglong2 w = wk[cp];   // .x={wfA,wfB} .y={whA,whB}
                    fma2(accf[cp][0], w.x, fd[kx]);
                    fma2(accf[cp][1], w.x, fd[kx+1]);
                    fma2(acc0[cp][0], w.y, gd[kx]);
                    fma2(acc0[cp][1], w.y, gd[kx+1]);
                    fma2(acc1[cp][0], w.y, ed[kx]);
                    fma2(acc1[cp][1], w.y, ed[kx+1]);
                }
            }
        }
    }

    // ---- epilogue: ReLU + sum -> packed comp_h; reload f centers ----
    ull ch01[C], fc01[C];
    #pragma unroll
    for (int cp = 0; cp < 5; ++cp) {
        float chv[2][2];
        #pragma unroll
        for (int px = 0; px < 2; ++px) {
            float afA, afB, x0A, x0B, x1A, x1B;
            unpack2(accf[cp][px], afA, afB);
            unpack2(acc0[cp][px], x0A, x0B);
            unpack2(acc1[cp][px], x1A, x1B);
            chv[px][0] = fmaxf(afA + x0A, 0.f) + fmaxf(afA + x1A, 0.f);
            chv[px][1] = fmaxf(afB + x0B, 0.f) + fmaxf(afB + x1B, 0.f);
        }
        ch01[2*cp]   = pack2(chv[0][0], chv[1][0]);
        ch01[2*cp+1] = pack2(chv[0][1], chv[1][1]);
    }
    {
        const int cbase = (ty + 1)*PITCH + (txp + 1);
        #pragma unroll
        for (int ci = 0; ci < C; ++ci) {
            const float* fc = f_s + ci*HS + cbase;
            fc01[ci] = pack2(fc[0], fc[1]);
        }
    }

    // ---- ConvGRU gates (1x1), packed f32x2, HW tanh sigmoids ----
    ull r01[C], u01[C];
    #pragma unroll
    for (int co = 0; co < C2; ++co) {
        float gb = gb_s[co];
        ull g = pack2(gb, gb);
        const ulonglong2* w = reinterpret_cast<const ulonglong2*>(wg2) + co*C;
        #pragma unroll
        for (int ci = 0; ci < C; ++ci) {
            ulonglong2 ww = w[ci];
            fma2(g, ww.x, ch01[ci]);
            fma2(g, ww.y, fc01[ci]);
        }
        float gg0, gg1; unpack2(g, gg0, gg1);
        ull s = pack2(fsigmoid(gg0), fsigmoid(gg1));
        if (co < C) r01[co] = s; else u01[co - C] = s;
    }
    ull rf01[C];
    #pragma unroll
    for (int ci = 0; ci < C; ++ci) rf01[ci] = mul2(r01[ci], fc01[ci]);

    // ---- candidate + update, write output ----
    const int gy = ty0 + ty, gx = tx0 + txp;
    #pragma unroll
    for (int co = 0; co < C; ++co) {
        float cb = cb_s[co];
        ull g = pack2(cb, cb);
        const ulonglong2* w = reinterpret_cast<const ulonglong2*>(wc2) + co*C;
        #pragma unroll
        for (int ci = 0; ci < C; ++ci) {
            ulonglong2 ww = w[ci];
            fma2(g, ww.x, ch01[ci]);
            fma2(g, ww.y, rf01[ci]);
        }
        float gg0, gg1; unpack2(g, gg0, gg1);
        float t0 = htanh(gg0), t1 = htanh(gg1);
        float fc0, fc1; unpack2(fc01[co], fc0, fc1);
        float u0, u1;  unpack2(u01[co], u0, u1);
        float r0 = fc0 + u0*(t0 - fc0);
        float r1 = fc1 + u1*(t1 - fc1);
        long o = ((long)(b*C + co)*HW + gy)*HW + gx;
        *reinterpret_cast<float2*>(out_f + o) = make_float2(r0, r1);
    }
}

extern "C" void kernel_launch(void* const* d_in, const int* in_sizes, int n_in,
                              void* d_out, int out_size) {
    (void)n_in; (void)out_size;
    const float* f_node   = (const float*)d_in[0];
    const float* h0       = (const float*)d_in[1];
    const float* h1       = (const float*)d_in[2];
    // d_in[3] = p_nodes (unused), d_in[4] = xf (unused)
    const float* att_w    = (const float*)d_in[5];
    const float* att_b    = (const float*)d_in[6];
    const float* rel_w    = (const float*)d_in[7];
    const float* bn_gamma = (const float*)d_in[8];
    const float* bn_beta  = (const float*)d_in[9];
    const float* bn_mean  = (const float*)d_in[10];
    const float* bn_var   = (const float*)d_in[11];
    const float* gates_w  = (const float*)d_in[12];
    const float* gates_b  = (const float*)d_in[13];
    const float* can_w    = (const float*)d_in[14];
    const float* can_b    = (const float*)d_in[15];

    int B = in_sizes[0] / (C * HW * HW);
    float* out_f   = (float*)d_out;
    float* out_att = out_f + (long)B * C * HW * HW;

    static bool attr_set = false;
    if (!attr_set) {
        cudaFuncSetAttribute(fused_tree_gru,
                             cudaFuncAttributeMaxDynamicSharedMemorySize, SMEM_BYTES);
        attr_set = true;
    }

    dim3 grid(HW / TW, HW / TH, B);
    fused_tree_gru<<<grid, NTHR, SMEM_BYTES>>>(f_node, h0, h1, att_w, att_b, rel_w,
                                               bn_gamma, bn_beta, bn_mean, bn_var,
                                               gates_w, gates_b, can_w, can_b,
                                               out_f, out_att);
}